// round 1
// baseline (speedup 1.0000x reference)
#include <cuda_runtime.h>
#include <cstdint>

#define NQ   32
#define KCB  1024
#define CD   8
#define DD   1024
#define TT   4096
#define BB   8

#define KM       4            // columns per warp
#define NWARPS   8
#define NTHREADS 256
#define COLS_PB  (KM * NWARPS)          // 32 columns per block
#define NBLOCKS  ((BB * TT) / COLS_PB)  // 1024

#define QOUT_ELEMS (BB * DD * TT)       // 33554432
#define IDX_ELEMS  (NQ * BB * TT)       // 1048576
#define FULL_OUT   (QOUT_ELEMS + IDX_ELEMS + BB)

// SMEM: W_inT (1024x12), W_out (1024x12), cbn (1024x12), cbn2 (1024), b_out (1024), b_in (8)
#define SMEM_FLOATS (DD*12 + DD*12 + KCB*12 + KCB + DD + 8)
#define SMEM_BYTES  (SMEM_FLOATS * 4)

// Precomputed scratch (device globals: no allocation allowed)
__device__ float g_winT[NQ * DD * CD];   // [nq][d][c]
__device__ float g_cbn [NQ * KCB * CD];  // normalized codebooks [nq][k][c]
__device__ float g_cbn2[NQ * KCB];       // sum of squares of normalized rows
__device__ int   g_len [BB];

// ---------------------------------------------------------------------------
// Precompute: W_in transpose, normalized codebooks, length decode + echo
// ---------------------------------------------------------------------------
__global__ void rvq_precompute(const float* __restrict__ W_in,
                               const float* __restrict__ cb,
                               const long long* __restrict__ len64,
                               float* __restrict__ out, int out_size) {
    int tid = blockIdx.x * blockDim.x + threadIdx.x;   // 0 .. 262143
    // W_in transpose: [nq][c][d] -> [nq][d][c]
    int nq  = tid >> 13;
    int rem = tid & 8191;
    int d   = rem >> 3;
    int c   = rem & 7;
    g_winT[tid] = W_in[(nq * CD + c) * DD + d];

    if (tid < NQ * KCB) {
        const float* row = cb + (size_t)tid * CD;
        float v[8];
        float n2 = 0.0f;
#pragma unroll
        for (int i = 0; i < 8; i++) { v[i] = row[i]; n2 = fmaf(v[i], v[i], n2); }
        float nrm = __fsqrt_rn(n2);
        float s   = fmaxf(nrm, 1e-12f);
        float c2  = 0.0f;
#pragma unroll
        for (int i = 0; i < 8; i++) {
            float e = __fdiv_rn(v[i], s);
            g_cbn[(size_t)tid * CD + i] = e;
            c2 = fmaf(e, e, c2);
        }
        g_cbn2[tid] = c2;
    }

    if (tid == 0) {
        // Detect int64 vs int32 input_length (JAX x64 on/off)
        long long tmp[BB];
        bool ok64 = true;
        for (int i = 0; i < BB; i++) {
            tmp[i] = len64[i];
            if (tmp[i] < 0 || tmp[i] > TT) ok64 = false;
        }
        if (ok64) {
            for (int i = 0; i < BB; i++) g_len[i] = (int)tmp[i];
        } else {
            const int* l32 = (const int*)len64;
            for (int i = 0; i < BB; i++) g_len[i] = l32[i];
        }
        if (out_size >= FULL_OUT) {
            for (int i = 0; i < BB; i++)
                out[QOUT_ELEMS + IDX_ELEMS + i] = (float)g_len[i];
        }
    }
}

// ---------------------------------------------------------------------------
// Main fused RVQ kernel: one warp owns KM=4 consecutive t-columns.
// Residual lives in registers (32 floats / lane / column).
// ---------------------------------------------------------------------------
__global__ void __launch_bounds__(NTHREADS, 1)
rvq_kernel(const float* __restrict__ z,
           const float* __restrict__ b_in,
           const float* __restrict__ W_out,
           const float* __restrict__ b_out,
           const float* __restrict__ cb,
           float* __restrict__ out, int out_size) {
    extern __shared__ float sm[];
    float* sWinT = sm;                     // [d*12 + c]
    float* sWout = sWinT + DD * 12;        // [d*12 + c]
    float* sCbn  = sWout + DD * 12;        // [k*12 + c]
    float* sCbn2 = sCbn  + KCB * 12;       // [k]
    float* sBout = sCbn2 + KCB;            // [d]
    float* sBin  = sBout + DD;             // [c]

    const int lane = threadIdx.x & 31;
    const int warp = threadIdx.x >> 5;
    const int b    = blockIdx.x >> 7;                  // 128 blocks per batch
    const int t0   = ((blockIdx.x & 127) * COLS_PB) + warp * KM;

    const int len = g_len[b];
    float maskf[KM];
#pragma unroll
    for (int j = 0; j < KM; j++) maskf[j] = ((t0 + j) < len) ? 1.0f : 0.0f;

    // Load residual = z * mask (masked columns carry r==0; fixed up at the end)
    float r[KM][32];
    const float* zbase = z + ((size_t)b * DD) * TT + t0;
#pragma unroll
    for (int i = 0; i < 32; i++) {
        int d = lane + 32 * i;
        float4 v = *reinterpret_cast<const float4*>(zbase + (size_t)d * TT);
        r[0][i] = v.x * maskf[0];
        r[1][i] = v.y * maskf[1];
        r[2][i] = v.z * maskf[2];
        r[3][i] = v.w * maskf[3];
    }

    const bool write_idx = (out_size >= QOUT_ELEMS + IDX_ELEMS);

    for (int nq = 0; nq < NQ; nq++) {
        // ---- stage this step's weights into SMEM (padded rows: 12 floats) ----
        {
            const float4* srcA = reinterpret_cast<const float4*>(g_winT + (size_t)nq * DD * CD);
            const float4* srcB = reinterpret_cast<const float4*>(W_out  + (size_t)nq * DD * CD);
            const float4* srcC = reinterpret_cast<const float4*>(g_cbn  + (size_t)nq * KCB * CD);
#pragma unroll
            for (int it = 0; it < 8; it++) {
                int f    = it * NTHREADS + threadIdx.x;  // 0..2047
                int half = f >> 10;                      // 0/1
                int row  = f & 1023;
                int sidx = row * 2 + half;
                *reinterpret_cast<float4*>(&sWinT[row * 12 + half * 4]) = srcA[sidx];
                *reinterpret_cast<float4*>(&sWout[row * 12 + half * 4]) = srcB[sidx];
                *reinterpret_cast<float4*>(&sCbn [row * 12 + half * 4]) = srcC[sidx];
            }
            reinterpret_cast<float4*>(sCbn2)[threadIdx.x] =
                reinterpret_cast<const float4*>(g_cbn2 + (size_t)nq * KCB)[threadIdx.x];
            reinterpret_cast<float4*>(sBout)[threadIdx.x] =
                reinterpret_cast<const float4*>(b_out + (size_t)nq * DD)[threadIdx.x];
            if (threadIdx.x < 2)
                reinterpret_cast<float4*>(sBin)[threadIdx.x] =
                    reinterpret_cast<const float4*>(b_in + (size_t)nq * CD)[threadIdx.x];
        }
        __syncthreads();

        // ---- in_proj: ze[c] = sum_d W_in[c,d] * (r*mask)[d] + b_in[c] ----
        float ze[KM][8];
#pragma unroll
        for (int j = 0; j < KM; j++)
#pragma unroll
            for (int c = 0; c < 8; c++) ze[j][c] = 0.0f;

#pragma unroll
        for (int i = 0; i < 32; i++) {
            int d = lane + 32 * i;
            float4 w0 = *reinterpret_cast<const float4*>(&sWinT[d * 12]);
            float4 w1 = *reinterpret_cast<const float4*>(&sWinT[d * 12 + 4]);
#pragma unroll
            for (int j = 0; j < KM; j++) {
                float f = r[j][i];   // already mask-scaled (masked columns: 0)
                ze[j][0] = fmaf(w0.x, f, ze[j][0]);
                ze[j][1] = fmaf(w0.y, f, ze[j][1]);
                ze[j][2] = fmaf(w0.z, f, ze[j][2]);
                ze[j][3] = fmaf(w0.w, f, ze[j][3]);
                ze[j][4] = fmaf(w1.x, f, ze[j][4]);
                ze[j][5] = fmaf(w1.y, f, ze[j][5]);
                ze[j][6] = fmaf(w1.z, f, ze[j][6]);
                ze[j][7] = fmaf(w1.w, f, ze[j][7]);
            }
        }
        // warp-reduce partials (butterfly -> all lanes hold full sums)
#pragma unroll
        for (int off = 16; off > 0; off >>= 1) {
#pragma unroll
            for (int j = 0; j < KM; j++)
#pragma unroll
                for (int c = 0; c < 8; c++)
                    ze[j][c] += __shfl_xor_sync(0xffffffffu, ze[j][c], off);
        }
#pragma unroll
        for (int j = 0; j < KM; j++)
#pragma unroll
            for (int c = 0; c < 8; c++) ze[j][c] += sBin[c];

        // ---- normalization factor (argmin uses dist = const - 2*inv*dot + |cbn|^2) ----
        float m2[KM];
#pragma unroll
        for (int j = 0; j < KM; j++) {
            float n2 = 0.0f;
#pragma unroll
            for (int c = 0; c < 8; c++) n2 = fmaf(ze[j][c], ze[j][c], n2);
            float s   = fmaxf(__fsqrt_rn(n2), 1e-12f);
            float inv = __fdiv_rn(1.0f, s);
            m2[j] = -2.0f * inv;
        }

        // ---- argmin over K=1024 codewords (32 per lane, ascending k) ----
        float best[KM];
        int   bk[KM];
#pragma unroll
        for (int j = 0; j < KM; j++) { best[j] = 3.4e38f; bk[j] = 0; }

#pragma unroll 4
        for (int jj = 0; jj < 32; jj++) {
            int k = lane + 32 * jj;
            float4 c0  = *reinterpret_cast<const float4*>(&sCbn[k * 12]);
            float4 c1  = *reinterpret_cast<const float4*>(&sCbn[k * 12 + 4]);
            float  c2v = sCbn2[k];
#pragma unroll
            for (int j = 0; j < KM; j++) {
                float dp = ze[j][0] * c0.x;
                dp = fmaf(ze[j][1], c0.y, dp);
                dp = fmaf(ze[j][2], c0.z, dp);
                dp = fmaf(ze[j][3], c0.w, dp);
                dp = fmaf(ze[j][4], c1.x, dp);
                dp = fmaf(ze[j][5], c1.y, dp);
                dp = fmaf(ze[j][6], c1.z, dp);
                dp = fmaf(ze[j][7], c1.w, dp);
                float score = fmaf(m2[j], dp, c2v);
                if (score < best[j]) { best[j] = score; bk[j] = k; }
            }
        }
        // warp argmin reduce (ties -> smaller k, matching jnp.argmax first-hit)
#pragma unroll
        for (int off = 16; off > 0; off >>= 1) {
#pragma unroll
            for (int j = 0; j < KM; j++) {
                float ob = __shfl_xor_sync(0xffffffffu, best[j], off);
                int   ok = __shfl_xor_sync(0xffffffffu, bk[j],  off);
                if (ob < best[j] || (ob == best[j] && ok < bk[j])) {
                    best[j] = ob; bk[j] = ok;
                }
            }
        }

        // ---- gather raw codewords (broadcast LDG), scale by mask ----
        float zq[KM][8];
#pragma unroll
        for (int j = 0; j < KM; j++) {
            const float4* p = reinterpret_cast<const float4*>(
                cb + ((size_t)nq * KCB + bk[j]) * CD);
            float4 a = __ldg(p);
            float4 bb4 = __ldg(p + 1);
            float mf = maskf[j];
            zq[j][0] = a.x * mf;  zq[j][1] = a.y * mf;
            zq[j][2] = a.z * mf;  zq[j][3] = a.w * mf;
            zq[j][4] = bb4.x * mf; zq[j][5] = bb4.y * mf;
            zq[j][6] = bb4.z * mf; zq[j][7] = bb4.w * mf;
        }

        if (lane == 0 && write_idx) {
            float4 iv = make_float4((float)bk[0], (float)bk[1],
                                    (float)bk[2], (float)bk[3]);
            *reinterpret_cast<float4*>(
                &out[QOUT_ELEMS + ((size_t)(nq * BB + b)) * TT + t0]) = iv;
        }

        // ---- out_proj + residual update: r -= (W_out @ (zq*mask) + b_out*mask) ----
#pragma unroll
        for (int i = 0; i < 32; i++) {
            int d = lane + 32 * i;
            float4 w0 = *reinterpret_cast<const float4*>(&sWout[d * 12]);
            float4 w1 = *reinterpret_cast<const float4*>(&sWout[d * 12 + 4]);
            float  bo = sBout[d];
#pragma unroll
            for (int j = 0; j < KM; j++) {
                float acc = w0.x * zq[j][0];
                acc = fmaf(w0.y, zq[j][1], acc);
                acc = fmaf(w0.z, zq[j][2], acc);
                acc = fmaf(w0.w, zq[j][3], acc);
                acc = fmaf(w1.x, zq[j][4], acc);
                acc = fmaf(w1.y, zq[j][5], acc);
                acc = fmaf(w1.z, zq[j][6], acc);
                acc = fmaf(w1.w, zq[j][7], acc);
                acc = fmaf(bo, maskf[j], acc);
                r[j][i] -= acc;
            }
        }
        __syncthreads();
    }

    // ---- qout = (z - r_final) * mask  (masked: r==0 so (z-0)*0 == 0) ----
    if (out_size >= QOUT_ELEMS) {
        float* qb = out + ((size_t)b * DD) * TT + t0;
#pragma unroll
        for (int i = 0; i < 32; i++) {
            int d = lane + 32 * i;
            float4 v = *reinterpret_cast<const float4*>(zbase + (size_t)d * TT);
            float4 o;
            o.x = (v.x - r[0][i]) * maskf[0];
            o.y = (v.y - r[1][i]) * maskf[1];
            o.z = (v.z - r[2][i]) * maskf[2];
            o.w = (v.w - r[3][i]) * maskf[3];
            *reinterpret_cast<float4*>(qb + (size_t)d * TT) = o;
        }
    }
}

// ---------------------------------------------------------------------------
extern "C" void kernel_launch(void* const* d_in, const int* in_sizes, int n_in,
                              void* d_out, int out_size) {
    const float*     z     = (const float*)d_in[0];
    const long long* len   = (const long long*)d_in[1];
    const float*     W_in  = (const float*)d_in[2];
    const float*     b_in  = (const float*)d_in[3];
    const float*     W_out = (const float*)d_in[4];
    const float*     b_out = (const float*)d_in[5];
    const float*     cbk   = (const float*)d_in[6];
    float* out = (float*)d_out;

    cudaFuncSetAttribute(rvq_kernel,
                         cudaFuncAttributeMaxDynamicSharedMemorySize, SMEM_BYTES);

    rvq_precompute<<<(NQ * DD * CD) / NTHREADS, NTHREADS>>>(W_in, cbk, len, out, out_size);
    rvq_kernel<<<NBLOCKS, NTHREADS, SMEM_BYTES>>>(z, b_in, W_out, b_out, cbk, out, out_size);
}

// round 2
// speedup vs baseline: 2.0454x; 2.0454x over previous
#include <cuda_runtime.h>
#include <cstdint>

#define NQ   32
#define KCB  1024
#define CD   8
#define DD   1024
#define TT   4096
#define BB   8

#define KM       4            // columns per warp
#define NWARPS   8
#define NTHREADS 256
#define COLS_PB  (KM * NWARPS)          // 32 columns per block
#define NBLOCKS  ((BB * TT) / COLS_PB)  // 1024

#define QOUT_ELEMS (BB * DD * TT)       // 33554432
#define IDX_ELEMS  (NQ * BB * TT)       // 1048576
#define FULL_OUT   (QOUT_ELEMS + IDX_ELEMS + BB)

// SMEM: W_inT (1024x12 padded), W_out (1024x12), cbn (1024x12), b_out (1024), b_in (8)
#define SMEM_FLOATS (DD*12 + DD*12 + KCB*12 + DD + 8)
#define SMEM_BYTES  (SMEM_FLOATS * 4)

typedef unsigned long long u64t;

// ---- f32x2 packed helpers (FFMA2 path: only reachable via PTX) ----
__device__ __forceinline__ u64t pk2(float a, float b) {
    u64t r; asm("mov.b64 %0,{%1,%2};" : "=l"(r) : "f"(a), "f"(b)); return r;
}
__device__ __forceinline__ float2 upk2(u64t v) {
    float2 r; asm("mov.b64 {%0,%1},%2;" : "=f"(r.x), "=f"(r.y) : "l"(v)); return r;
}
__device__ __forceinline__ void fma2(u64t& d, u64t a, u64t b) {
    asm("fma.rn.f32x2 %0,%1,%2,%0;" : "+l"(d) : "l"(a), "l"(b));
}
__device__ __forceinline__ u64t mul2(u64t a, u64t b) {
    u64t r; asm("mul.rn.f32x2 %0,%1,%2;" : "=l"(r) : "l"(a), "l"(b)); return r;
}

// Precomputed scratch (device globals: no allocation allowed)
__device__ float g_winT[NQ * DD * CD];   // [nq][d][c]
__device__ float g_cbn [NQ * KCB * CD];  // normalized codebooks [nq][k][c]
__device__ int   g_len [BB];

// ---------------------------------------------------------------------------
// Precompute: W_in transpose, normalized codebooks, length decode + echo
// ---------------------------------------------------------------------------
__global__ void rvq_precompute(const float* __restrict__ W_in,
                               const float* __restrict__ cb,
                               const long long* __restrict__ len64,
                               float* __restrict__ out, int out_size) {
    int tid = blockIdx.x * blockDim.x + threadIdx.x;   // 0 .. 262143
    // W_in transpose: [nq][c][d] -> [nq][d][c]
    int nq  = tid >> 13;
    int rem = tid & 8191;
    int d   = rem >> 3;
    int c   = rem & 7;
    g_winT[tid] = W_in[(nq * CD + c) * DD + d];

    if (tid < NQ * KCB) {
        const float* row = cb + (size_t)tid * CD;
        float v[8];
        float n2 = 0.0f;
#pragma unroll
        for (int i = 0; i < 8; i++) { v[i] = row[i]; n2 = fmaf(v[i], v[i], n2); }
        float nrm = __fsqrt_rn(n2);
        float s   = fmaxf(nrm, 1e-12f);
#pragma unroll
        for (int i = 0; i < 8; i++)
            g_cbn[(size_t)tid * CD + i] = __fdiv_rn(v[i], s);
    }

    if (tid == 0) {
        // Detect int64 vs int32 input_length (JAX x64 on/off)
        long long tmp[BB];
        bool ok64 = true;
        for (int i = 0; i < BB; i++) {
            tmp[i] = len64[i];
            if (tmp[i] < 0 || tmp[i] > TT) ok64 = false;
        }
        if (ok64) {
            for (int i = 0; i < BB; i++) g_len[i] = (int)tmp[i];
        } else {
            const int* l32 = (const int*)len64;
            for (int i = 0; i < BB; i++) g_len[i] = l32[i];
        }
        if (out_size >= FULL_OUT) {
            for (int i = 0; i < BB; i++)
                out[QOUT_ELEMS + IDX_ELEMS + i] = (float)g_len[i];
        }
    }
}

// ---------------------------------------------------------------------------
// Main fused RVQ kernel: one warp owns KM=4 consecutive t-columns.
// Residual lives in registers (32 floats / lane / column).
// All inner products use packed fp32x2 FMA.
// ---------------------------------------------------------------------------
__global__ void __launch_bounds__(NTHREADS, 1)
rvq_kernel(const float* __restrict__ z,
           const float* __restrict__ b_in,
           const float* __restrict__ W_out,
           const float* __restrict__ b_out,
           const float* __restrict__ cb,
           float* __restrict__ out, int out_size) {
    extern __shared__ float sm[];
    float* sWinT = sm;                     // [d*12 + c]
    float* sWout = sWinT + DD * 12;        // [d*12 + c]
    float* sCbn  = sWout + DD * 12;        // [k*12 + c]
    float* sBout = sCbn  + KCB * 12;       // [d]
    float* sBin  = sBout + DD;             // [c]

    const int lane = threadIdx.x & 31;
    const int warp = threadIdx.x >> 5;
    const int b    = blockIdx.x >> 7;                  // 128 blocks per batch
    const int t0   = ((blockIdx.x & 127) * COLS_PB) + warp * KM;

    const int len = g_len[b];
    float maskf[KM], nmf[KM];
#pragma unroll
    for (int j = 0; j < KM; j++) {
        maskf[j] = ((t0 + j) < len) ? 1.0f : 0.0f;
        nmf[j]   = -maskf[j];
    }

    // Load residual = z * mask (masked columns carry r==0; fixed up at the end)
    float r[KM][32];
    const float* zbase = z + ((size_t)b * DD) * TT + t0;
#pragma unroll
    for (int i = 0; i < 32; i++) {
        int d = lane + 32 * i;
        float4 v = *reinterpret_cast<const float4*>(zbase + (size_t)d * TT);
        r[0][i] = v.x * maskf[0];
        r[1][i] = v.y * maskf[1];
        r[2][i] = v.z * maskf[2];
        r[3][i] = v.w * maskf[3];
    }

    const bool write_idx = (out_size >= QOUT_ELEMS + IDX_ELEMS);

    for (int nq = 0; nq < NQ; nq++) {
        // ---- stage this step's weights into SMEM (padded rows: 12 floats) ----
        {
            const float4* srcA = reinterpret_cast<const float4*>(g_winT + (size_t)nq * DD * CD);
            const float4* srcB = reinterpret_cast<const float4*>(W_out  + (size_t)nq * DD * CD);
            const float4* srcC = reinterpret_cast<const float4*>(g_cbn  + (size_t)nq * KCB * CD);
#pragma unroll
            for (int it = 0; it < 8; it++) {
                int f    = it * NTHREADS + threadIdx.x;  // 0..2047
                int half = f >> 10;                      // 0/1
                int row  = f & 1023;
                int sidx = row * 2 + half;
                *reinterpret_cast<float4*>(&sWinT[row * 12 + half * 4]) = srcA[sidx];
                *reinterpret_cast<float4*>(&sWout[row * 12 + half * 4]) = srcB[sidx];
                *reinterpret_cast<float4*>(&sCbn [row * 12 + half * 4]) = srcC[sidx];
            }
            reinterpret_cast<float4*>(sBout)[threadIdx.x] =
                reinterpret_cast<const float4*>(b_out + (size_t)nq * DD)[threadIdx.x];
            if (threadIdx.x < 2)
                reinterpret_cast<float4*>(sBin)[threadIdx.x] =
                    reinterpret_cast<const float4*>(b_in + (size_t)nq * CD)[threadIdx.x];
        }
        __syncthreads();

        // ---- in_proj: ze[c] = sum_d W_in[c,d] * r[d]   (packed over channel pairs)
        u64t zeA[KM][4];
#pragma unroll
        for (int j = 0; j < KM; j++)
#pragma unroll
            for (int p = 0; p < 4; p++) zeA[j][p] = 0ull;

#pragma unroll
        for (int i = 0; i < 32; i++) {
            int d = lane + 32 * i;
            ulonglong2 wA = *reinterpret_cast<const ulonglong2*>(&sWinT[d * 12]);
            ulonglong2 wB = *reinterpret_cast<const ulonglong2*>(&sWinT[d * 12 + 4]);
#pragma unroll
            for (int j = 0; j < KM; j++) {
                u64t rd = pk2(r[j][i], r[j][i]);
                fma2(zeA[j][0], wA.x, rd);
                fma2(zeA[j][1], wA.y, rd);
                fma2(zeA[j][2], wB.x, rd);
                fma2(zeA[j][3], wB.y, rd);
            }
        }

        // unpack to scalars (each half is a complete per-channel partial sum)
        float ze[KM][8];
#pragma unroll
        for (int j = 0; j < KM; j++)
#pragma unroll
            for (int p = 0; p < 4; p++) {
                float2 u = upk2(zeA[j][p]);
                ze[j][2 * p]     = u.x;
                ze[j][2 * p + 1] = u.y;
            }

        // warp-reduce partials (butterfly -> all lanes hold full sums)
#pragma unroll
        for (int off = 16; off > 0; off >>= 1) {
#pragma unroll
            for (int j = 0; j < KM; j++)
#pragma unroll
                for (int c = 0; c < 8; c++)
                    ze[j][c] += __shfl_xor_sync(0xffffffffu, ze[j][c], off);
        }

        // add bias and re-pack channel pairs for the argmax stage
        u64t zp[KM][4];
#pragma unroll
        for (int j = 0; j < KM; j++)
#pragma unroll
            for (int p = 0; p < 4; p++)
                zp[j][p] = pk2(ze[j][2 * p]     + sBin[2 * p],
                               ze[j][2 * p + 1] + sBin[2 * p + 1]);

        // ---- argmax over dot(ze, cbn_k)  (== argmin of reference distance) ----
        float best[KM];
        int   bk[KM];
#pragma unroll
        for (int j = 0; j < KM; j++) { best[j] = -3.4e38f; bk[j] = 0; }

#pragma unroll
        for (int jj = 0; jj < 32; jj++) {
            int k = lane + 32 * jj;                  // ascending per lane
            ulonglong2 cA = *reinterpret_cast<const ulonglong2*>(&sCbn[k * 12]);
            ulonglong2 cB = *reinterpret_cast<const ulonglong2*>(&sCbn[k * 12 + 4]);
#pragma unroll
            for (int j = 0; j < KM; j++) {
                u64t dpp = mul2(zp[j][0], cA.x);
                fma2(dpp, zp[j][1], cA.y);
                fma2(dpp, zp[j][2], cB.x);
                fma2(dpp, zp[j][3], cB.y);
                float2 u = upk2(dpp);
                float dp = u.x + u.y;
                if (dp > best[j]) { best[j] = dp; bk[j] = k; }  // strict: first max
            }
        }
        // warp argmax reduce (ties -> smaller k, matching jnp.argmax first-hit)
#pragma unroll
        for (int off = 16; off > 0; off >>= 1) {
#pragma unroll
            for (int j = 0; j < KM; j++) {
                float ob = __shfl_xor_sync(0xffffffffu, best[j], off);
                int   ok = __shfl_xor_sync(0xffffffffu, bk[j],  off);
                if (ob > best[j] || (ob == best[j] && ok < bk[j])) {
                    best[j] = ob; bk[j] = ok;
                }
            }
        }

        // ---- gather raw codewords (broadcast LDG), negated & mask-scaled, packed ----
        u64t zqn[KM][4];
#pragma unroll
        for (int j = 0; j < KM; j++) {
            const ulonglong2* p = reinterpret_cast<const ulonglong2*>(
                cb + ((size_t)nq * KCB + bk[j]) * CD);
            ulonglong2 qa = __ldg(p);        // {c0,c1},{c2,c3}
            ulonglong2 qb = __ldg(p + 1);    // {c4,c5},{c6,c7}
            u64t nm = pk2(nmf[j], nmf[j]);
            zqn[j][0] = mul2(qa.x, nm);
            zqn[j][1] = mul2(qa.y, nm);
            zqn[j][2] = mul2(qb.x, nm);
            zqn[j][3] = mul2(qb.y, nm);
        }

        if (lane == 0 && write_idx) {
            float4 iv = make_float4((float)bk[0], (float)bk[1],
                                    (float)bk[2], (float)bk[3]);
            *reinterpret_cast<float4*>(
                &out[QOUT_ELEMS + ((size_t)(nq * BB + b)) * TT + t0]) = iv;
        }

        // ---- out_proj + residual update: r += -(W_out @ (zq*mask)) - b_out*mask ----
#pragma unroll
        for (int i = 0; i < 32; i++) {
            int d = lane + 32 * i;
            ulonglong2 wA = *reinterpret_cast<const ulonglong2*>(&sWout[d * 12]);
            ulonglong2 wB = *reinterpret_cast<const ulonglong2*>(&sWout[d * 12 + 4]);
            float bo = sBout[d];
#pragma unroll
            for (int j = 0; j < KM; j++) {
                u64t acc = mul2(wA.x, zqn[j][0]);
                fma2(acc, wA.y, zqn[j][1]);
                fma2(acc, wB.x, zqn[j][2]);
                fma2(acc, wB.y, zqn[j][3]);
                float2 u = upk2(acc);
                r[j][i] = fmaf(bo, nmf[j], r[j][i] + (u.x + u.y));
            }
        }
        __syncthreads();
    }

    // ---- qout = (z - r_final) * mask  (masked: r==0 so (z-0)*0 == 0) ----
    if (out_size >= QOUT_ELEMS) {
        float* qb = out + ((size_t)b * DD) * TT + t0;
#pragma unroll
        for (int i = 0; i < 32; i++) {
            int d = lane + 32 * i;
            float4 v = *reinterpret_cast<const float4*>(zbase + (size_t)d * TT);
            float4 o;
            o.x = (v.x - r[0][i]) * maskf[0];
            o.y = (v.y - r[1][i]) * maskf[1];
            o.z = (v.z - r[2][i]) * maskf[2];
            o.w = (v.w - r[3][i]) * maskf[3];
            *reinterpret_cast<float4*>(qb + (size_t)d * TT) = o;
        }
    }
}

// ---------------------------------------------------------------------------
extern "C" void kernel_launch(void* const* d_in, const int* in_sizes, int n_in,
                              void* d_out, int out_size) {
    const float*     z     = (const float*)d_in[0];
    const long long* len   = (const long long*)d_in[1];
    const float*     W_in  = (const float*)d_in[2];
    const float*     b_in  = (const float*)d_in[3];
    const float*     W_out = (const float*)d_in[4];
    const float*     b_out = (const float*)d_in[5];
    const float*     cbk   = (const float*)d_in[6];
    float* out = (float*)d_out;

    cudaFuncSetAttribute(rvq_kernel,
                         cudaFuncAttributeMaxDynamicSharedMemorySize, SMEM_BYTES);

    rvq_precompute<<<(NQ * DD * CD) / NTHREADS, NTHREADS>>>(W_in, cbk, len, out, out_size);
    rvq_kernel<<<NBLOCKS, NTHREADS, SMEM_BYTES>>>(z, b_in, W_out, b_out, cbk, out, out_size);
}

// round 3
// speedup vs baseline: 2.0539x; 1.0042x over previous
#include <cuda_runtime.h>
#include <cstdint>

#define NQ   32
#define KCB  1024
#define CD   8
#define DD   1024
#define TT   4096
#define BB   8

#define KM       4            // columns per warp
#define NWARPS   8
#define NTHREADS 256
#define COLS_PB  (KM * NWARPS)          // 32 columns per block
#define NBLOCKS  ((BB * TT) / COLS_PB)  // 1024

#define QOUT_ELEMS (BB * DD * TT)       // 33554432
#define IDX_ELEMS  (NQ * BB * TT)       // 1048576
#define FULL_OUT   (QOUT_ELEMS + IDX_ELEMS + BB)

// SMEM: W_inT (1024x12 padded), W_out (1024x12), cbn (1024x12), b_out (1024), b_in (8)
#define SMEM_FLOATS (DD*12 + DD*12 + KCB*12 + DD + 8)
#define SMEM_BYTES  (SMEM_FLOATS * 4)

typedef unsigned long long u64t;

// ---- f32x2 packed helpers (FFMA2 path: only reachable via PTX) ----
__device__ __forceinline__ u64t pk2(float a, float b) {
    u64t r; asm("mov.b64 %0,{%1,%2};" : "=l"(r) : "f"(a), "f"(b)); return r;
}
__device__ __forceinline__ float2 upk2(u64t v) {
    float2 r; asm("mov.b64 {%0,%1},%2;" : "=f"(r.x), "=f"(r.y) : "l"(v)); return r;
}
__device__ __forceinline__ void fma2(u64t& d, u64t a, u64t b) {
    asm("fma.rn.f32x2 %0,%1,%2,%0;" : "+l"(d) : "l"(a), "l"(b));
}
__device__ __forceinline__ u64t mul2(u64t a, u64t b) {
    u64t r; asm("mul.rn.f32x2 %0,%1,%2;" : "=l"(r) : "l"(a), "l"(b)); return r;
}

// Precomputed scratch (device globals: no allocation allowed)
__device__ float g_winT[NQ * DD * CD];   // [nq][d][c]
__device__ float g_cbn [NQ * KCB * CD];  // normalized codebooks [nq][k][c]
__device__ int   g_len [BB];

// ---------------------------------------------------------------------------
// Precompute: W_in transpose, normalized codebooks, length decode + echo
// ---------------------------------------------------------------------------
__global__ void rvq_precompute(const float* __restrict__ W_in,
                               const float* __restrict__ cb,
                               const long long* __restrict__ len64,
                               float* __restrict__ out, int out_size) {
    int tid = blockIdx.x * blockDim.x + threadIdx.x;   // 0 .. 262143
    // W_in transpose: [nq][c][d] -> [nq][d][c]
    int nq  = tid >> 13;
    int rem = tid & 8191;
    int d   = rem >> 3;
    int c   = rem & 7;
    g_winT[tid] = W_in[(nq * CD + c) * DD + d];

    if (tid < NQ * KCB) {
        const float* row = cb + (size_t)tid * CD;
        float v[8];
        float n2 = 0.0f;
#pragma unroll
        for (int i = 0; i < 8; i++) { v[i] = row[i]; n2 = fmaf(v[i], v[i], n2); }
        float nrm = __fsqrt_rn(n2);
        float s   = fmaxf(nrm, 1e-12f);
#pragma unroll
        for (int i = 0; i < 8; i++)
            g_cbn[(size_t)tid * CD + i] = __fdiv_rn(v[i], s);
    }

    if (tid == 0) {
        // Detect int64 vs int32 input_length (JAX x64 on/off)
        long long tmp[BB];
        bool ok64 = true;
        for (int i = 0; i < BB; i++) {
            tmp[i] = len64[i];
            if (tmp[i] < 0 || tmp[i] > TT) ok64 = false;
        }
        if (ok64) {
            for (int i = 0; i < BB; i++) g_len[i] = (int)tmp[i];
        } else {
            const int* l32 = (const int*)len64;
            for (int i = 0; i < BB; i++) g_len[i] = l32[i];
        }
        if (out_size >= FULL_OUT) {
            for (int i = 0; i < BB; i++)
                out[QOUT_ELEMS + IDX_ELEMS + i] = (float)g_len[i];
        }
    }
}

// ---------------------------------------------------------------------------
// Main fused RVQ kernel: one warp owns KM=4 consecutive t-columns.
// Residual lives in registers (32 floats / lane / column).
// All inner products use packed fp32x2 FMA.
// ---------------------------------------------------------------------------
__global__ void __launch_bounds__(NTHREADS, 1)
rvq_kernel(const float* __restrict__ z,
           const float* __restrict__ b_in,
           const float* __restrict__ W_out,
           const float* __restrict__ b_out,
           const float* __restrict__ cb,
           float* __restrict__ out, int out_size) {
    extern __shared__ float sm[];
    float* sWinT = sm;                     // [d*12 + c]
    float* sWout = sWinT + DD * 12;        // [d*12 + c]
    float* sCbn  = sWout + DD * 12;        // [k*12 + c]
    float* sBout = sCbn  + KCB * 12;       // [d]
    float* sBin  = sBout + DD;             // [c]

    const int lane = threadIdx.x & 31;
    const int warp = threadIdx.x >> 5;
    const int b    = blockIdx.x >> 7;                  // 128 blocks per batch
    const int t0   = ((blockIdx.x & 127) * COLS_PB) + warp * KM;

    const int len = g_len[b];
    float maskf[KM], nmf[KM];
#pragma unroll
    for (int j = 0; j < KM; j++) {
        maskf[j] = ((t0 + j) < len) ? 1.0f : 0.0f;
        nmf[j]   = -maskf[j];
    }

    // Load residual = z * mask (masked columns carry r==0; fixed up at the end)
    float r[KM][32];
    const float* zbase = z + ((size_t)b * DD) * TT + t0;
#pragma unroll
    for (int i = 0; i < 32; i++) {
        int d = lane + 32 * i;
        float4 v = *reinterpret_cast<const float4*>(zbase + (size_t)d * TT);
        r[0][i] = v.x * maskf[0];
        r[1][i] = v.y * maskf[1];
        r[2][i] = v.z * maskf[2];
        r[3][i] = v.w * maskf[3];
    }

    const bool write_idx = (out_size >= QOUT_ELEMS + IDX_ELEMS);

    for (int nq = 0; nq < NQ; nq++) {
        // ---- stage this step's weights into SMEM (padded rows: 12 floats) ----
        {
            const float4* srcA = reinterpret_cast<const float4*>(g_winT + (size_t)nq * DD * CD);
            const float4* srcB = reinterpret_cast<const float4*>(W_out  + (size_t)nq * DD * CD);
            const float4* srcC = reinterpret_cast<const float4*>(g_cbn  + (size_t)nq * KCB * CD);
#pragma unroll
            for (int it = 0; it < 8; it++) {
                int f    = it * NTHREADS + threadIdx.x;  // 0..2047
                int half = f >> 10;                      // 0/1
                int row  = f & 1023;
                int sidx = row * 2 + half;
                *reinterpret_cast<float4*>(&sWinT[row * 12 + half * 4]) = srcA[sidx];
                *reinterpret_cast<float4*>(&sWout[row * 12 + half * 4]) = srcB[sidx];
                *reinterpret_cast<float4*>(&sCbn [row * 12 + half * 4]) = srcC[sidx];
            }
            reinterpret_cast<float4*>(sBout)[threadIdx.x] =
                reinterpret_cast<const float4*>(b_out + (size_t)nq * DD)[threadIdx.x];
            if (threadIdx.x < 2)
                reinterpret_cast<float4*>(sBin)[threadIdx.x] =
                    reinterpret_cast<const float4*>(b_in + (size_t)nq * CD)[threadIdx.x];
        }
        __syncthreads();

        // ---- in_proj: ze[c] = sum_d W_in[c,d] * r[d]   (packed over channel pairs)
        u64t zeA[KM][4];
#pragma unroll
        for (int j = 0; j < KM; j++)
#pragma unroll
            for (int p = 0; p < 4; p++) zeA[j][p] = 0ull;

#pragma unroll
        for (int i = 0; i < 32; i++) {
            int d = lane + 32 * i;
            ulonglong2 wA = *reinterpret_cast<const ulonglong2*>(&sWinT[d * 12]);
            ulonglong2 wB = *reinterpret_cast<const ulonglong2*>(&sWinT[d * 12 + 4]);
#pragma unroll
            for (int j = 0; j < KM; j++) {
                u64t rd = pk2(r[j][i], r[j][i]);
                fma2(zeA[j][0], wA.x, rd);
                fma2(zeA[j][1], wA.y, rd);
                fma2(zeA[j][2], wB.x, rd);
                fma2(zeA[j][3], wB.y, rd);
            }
        }

        // unpack to scalars (each half is a complete per-channel partial sum)
        float ze[KM][8];
#pragma unroll
        for (int j = 0; j < KM; j++)
#pragma unroll
            for (int p = 0; p < 4; p++) {
                float2 u = upk2(zeA[j][p]);
                ze[j][2 * p]     = u.x;
                ze[j][2 * p + 1] = u.y;
            }

        // warp-reduce partials (butterfly -> all lanes hold full sums)
#pragma unroll
        for (int off = 16; off > 0; off >>= 1) {
#pragma unroll
            for (int j = 0; j < KM; j++)
#pragma unroll
                for (int c = 0; c < 8; c++)
                    ze[j][c] += __shfl_xor_sync(0xffffffffu, ze[j][c], off);
        }

        // add bias and re-pack channel pairs for the argmax stage
        u64t zp[KM][4];
#pragma unroll
        for (int j = 0; j < KM; j++)
#pragma unroll
            for (int p = 0; p < 4; p++)
                zp[j][p] = pk2(ze[j][2 * p]     + sBin[2 * p],
                               ze[j][2 * p + 1] + sBin[2 * p + 1]);

        // ---- argmax over dot(ze, cbn_k)  (== argmin of reference distance) ----
        float best[KM];
        int   bk[KM];
#pragma unroll
        for (int j = 0; j < KM; j++) { best[j] = -3.4e38f; bk[j] = 0; }

#pragma unroll
        for (int jj = 0; jj < 32; jj++) {
            int k = lane + 32 * jj;                  // ascending per lane
            ulonglong2 cA = *reinterpret_cast<const ulonglong2*>(&sCbn[k * 12]);
            ulonglong2 cB = *reinterpret_cast<const ulonglong2*>(&sCbn[k * 12 + 4]);
#pragma unroll
            for (int j = 0; j < KM; j++) {
                u64t dpp = mul2(zp[j][0], cA.x);
                fma2(dpp, zp[j][1], cA.y);
                fma2(dpp, zp[j][2], cB.x);
                fma2(dpp, zp[j][3], cB.y);
                float2 u = upk2(dpp);
                float dp = u.x + u.y;
                if (dp > best[j]) { best[j] = dp; bk[j] = k; }  // strict: first max
            }
        }
        // warp argmax reduce (ties -> smaller k, matching jnp.argmax first-hit)
#pragma unroll
        for (int off = 16; off > 0; off >>= 1) {
#pragma unroll
            for (int j = 0; j < KM; j++) {
                float ob = __shfl_xor_sync(0xffffffffu, best[j], off);
                int   ok = __shfl_xor_sync(0xffffffffu, bk[j],  off);
                if (ob > best[j] || (ob == best[j] && ok < bk[j])) {
                    best[j] = ob; bk[j] = ok;
                }
            }
        }

        // ---- gather raw codewords (broadcast LDG), negated & mask-scaled, packed ----
        u64t zqn[KM][4];
#pragma unroll
        for (int j = 0; j < KM; j++) {
            const ulonglong2* p = reinterpret_cast<const ulonglong2*>(
                cb + ((size_t)nq * KCB + bk[j]) * CD);
            ulonglong2 qa = __ldg(p);        // {c0,c1},{c2,c3}
            ulonglong2 qb = __ldg(p + 1);    // {c4,c5},{c6,c7}
            u64t nm = pk2(nmf[j], nmf[j]);
            zqn[j][0] = mul2(qa.x, nm);
            zqn[j][1] = mul2(qa.y, nm);
            zqn[j][2] = mul2(qb.x, nm);
            zqn[j][3] = mul2(qb.y, nm);
        }

        if (lane == 0 && write_idx) {
            float4 iv = make_float4((float)bk[0], (float)bk[1],
                                    (float)bk[2], (float)bk[3]);
            *reinterpret_cast<float4*>(
                &out[QOUT_ELEMS + ((size_t)(nq * BB + b)) * TT + t0]) = iv;
        }

        // ---- out_proj + residual update: r += -(W_out @ (zq*mask)) - b_out*mask ----
#pragma unroll
        for (int i = 0; i < 32; i++) {
            int d = lane + 32 * i;
            ulonglong2 wA = *reinterpret_cast<const ulonglong2*>(&sWout[d * 12]);
            ulonglong2 wB = *reinterpret_cast<const ulonglong2*>(&sWout[d * 12 + 4]);
            float bo = sBout[d];
#pragma unroll
            for (int j = 0; j < KM; j++) {
                u64t acc = mul2(wA.x, zqn[j][0]);
                fma2(acc, wA.y, zqn[j][1]);
                fma2(acc, wB.x, zqn[j][2]);
                fma2(acc, wB.y, zqn[j][3]);
                float2 u = upk2(acc);
                r[j][i] = fmaf(bo, nmf[j], r[j][i] + (u.x + u.y));
            }
        }
        __syncthreads();
    }

    // ---- qout = (z - r_final) * mask  (masked: r==0 so (z-0)*0 == 0) ----
    if (out_size >= QOUT_ELEMS) {
        float* qb = out + ((size_t)b * DD) * TT + t0;
#pragma unroll
        for (int i = 0; i < 32; i++) {
            int d = lane + 32 * i;
            float4 v = *reinterpret_cast<const float4*>(zbase + (size_t)d * TT);
            float4 o;
            o.x = (v.x - r[0][i]) * maskf[0];
            o.y = (v.y - r[1][i]) * maskf[1];
            o.z = (v.z - r[2][i]) * maskf[2];
            o.w = (v.w - r[3][i]) * maskf[3];
            *reinterpret_cast<float4*>(qb + (size_t)d * TT) = o;
        }
    }
}

// ---------------------------------------------------------------------------
extern "C" void kernel_launch(void* const* d_in, const int* in_sizes, int n_in,
                              void* d_out, int out_size) {
    const float*     z     = (const float*)d_in[0];
    const long long* len   = (const long long*)d_in[1];
    const float*     W_in  = (const float*)d_in[2];
    const float*     b_in  = (const float*)d_in[3];
    const float*     W_out = (const float*)d_in[4];
    const float*     b_out = (const float*)d_in[5];
    const float*     cbk   = (const float*)d_in[6];
    float* out = (float*)d_out;

    cudaFuncSetAttribute(rvq_kernel,
                         cudaFuncAttributeMaxDynamicSharedMemorySize, SMEM_BYTES);

    rvq_precompute<<<(NQ * DD * CD) / NTHREADS, NTHREADS>>>(W_in, cbk, len, out, out_size);
    rvq_kernel<<<NBLOCKS, NTHREADS, SMEM_BYTES>>>(z, b_in, W_out, b_out, cbk, out, out_size);
}